// round 1
// baseline (speedup 1.0000x reference)
#include <cuda_runtime.h>
#include <cstdint>

// ---------------------------------------------------------------------------
// GlobalGNN: only layer 1 of the reference affects the output.
//   w1   = attr[e_id1]
//   xW   = x @ gcn_W^T                       (rows < n1 needed)
//   deg  = segsum(w1, tgt1) + 1              (targets < n2)
//   dinv = rsqrt(deg)
//   g1[t]= sum_e xW[src]*dinv[src]*w*dinv[t] + xW[t]*dinv[t]^2 + gcn_b
//   s    = segsum(g1[src1], tgt1); cnt = segsum(1)
//   out  = l2norm( (s/max(cnt,1)) @ Wl1^T + bl1 + g1[:n2] @ Wr1^T )
// ---------------------------------------------------------------------------

#define H 128
#define MAXN0 131072
#define MAXN2 16384
#define GROWS 64
#define SW 132   // padded smem stride for transposed weights (bank-conflict-free)
#define SX 68    // padded smem stride for transposed activations

__device__ __align__(16) float g_xW[(size_t)MAXN0 * H];
__device__ __align__(16) float g_g1[(size_t)MAXN0 * H];
__device__ __align__(16) float g_s [(size_t)MAXN2 * H];
__device__ float g_deg [MAXN2];
__device__ float g_cnt [MAXN2];
__device__ float g_dinv[MAXN2];

__device__ __forceinline__ int clamp_n1(const int* p, int N0) {
    int v = *p;                 // tolerant of int64 packing (low word, LE)
    if (v <= 0 || v > N0) v = N0;
    return v;
}

// ---- K1: init scratch for targets -----------------------------------------
__global__ void k_init(int n2) {
    int idx = blockIdx.x * blockDim.x + threadIdx.x;
    int tot = n2 * H;
    if (idx < tot) { g_g1[idx] = 0.f; g_s[idx] = 0.f; }
    if (idx < n2)  { g_deg[idx] = 1.f; g_cnt[idx] = 0.f; }
}

// ---- K2: degree (weighted) + count ----------------------------------------
__global__ void k_degcnt(const float* __restrict__ attr, const int* __restrict__ eid,
                         const int* __restrict__ tgt, int E, int n2) {
    int e = blockIdx.x * blockDim.x + threadIdx.x;
    if (e >= E) return;
    int t = tgt[e];
    float w = attr[eid[e]];
    if (t < n2) {
        atomicAdd(&g_deg[t], w);
        atomicAdd(&g_cnt[t], 1.f);
    }
}

// ---- K3: dinv --------------------------------------------------------------
__global__ void k_dinv(int n2) {
    int i = blockIdx.x * blockDim.x + threadIdx.x;
    if (i < n2) g_dinv[i] = rsqrtf(g_deg[i]);
}

// ---- K4: xW = x @ W^T  (rows < n1) -----------------------------------------
__global__ void __launch_bounds__(256) k_gemm_xw(
    const float* __restrict__ x, const float* __restrict__ W,
    const int* __restrict__ n1p, int N0) {
    extern __shared__ float sm[];
    float* Wt = sm;              // [128][SW]  Wt[k*SW+j] = W[j*128+k]
    float* xs = sm + H * SW;     // [128][SX]  xs[k*SX+r] = x[(row0+r)*128+k]

    int n1 = clamp_n1(n1p, N0);
    int row0 = blockIdx.x * GROWS;
    if (row0 >= n1) return;
    int tid = threadIdx.x;

    for (int idx = tid; idx < H * H; idx += 256) {
        int j = idx >> 7, k = idx & 127;
        Wt[k * SW + j] = W[idx];
    }
    for (int idx = tid; idx < GROWS * H; idx += 256) {
        int r = idx >> 7, k = idx & 127;
        int row = row0 + r;
        xs[k * SX + r] = (row < N0) ? x[(size_t)row * H + k] : 0.f;
    }
    __syncthreads();

    int col_t = tid & 15;   // owns cols [col_t*8, col_t*8+8)
    int row_t = tid >> 4;   // owns rows [row_t*4, row_t*4+4) of tile
    float acc[4][8];
#pragma unroll
    for (int i = 0; i < 4; ++i)
#pragma unroll
        for (int j = 0; j < 8; ++j) acc[i][j] = 0.f;

    for (int k = 0; k < H; ++k) {
        float4 a4 = *(const float4*)&xs[k * SX + row_t * 4];
        float4 b0 = *(const float4*)&Wt[k * SW + col_t * 8];
        float4 b1 = *(const float4*)&Wt[k * SW + col_t * 8 + 4];
        float a[4] = {a4.x, a4.y, a4.z, a4.w};
        float b[8] = {b0.x, b0.y, b0.z, b0.w, b1.x, b1.y, b1.z, b1.w};
#pragma unroll
        for (int i = 0; i < 4; ++i)
#pragma unroll
            for (int j = 0; j < 8; ++j) acc[i][j] += a[i] * b[j];
    }

#pragma unroll
    for (int i = 0; i < 4; ++i) {
        int row = row0 + row_t * 4 + i;
        if (row < N0) {
            float4 o0 = make_float4(acc[i][0], acc[i][1], acc[i][2], acc[i][3]);
            float4 o1 = make_float4(acc[i][4], acc[i][5], acc[i][6], acc[i][7]);
            *(float4*)&g_xW[(size_t)row * H + col_t * 8]     = o0;
            *(float4*)&g_xW[(size_t)row * H + col_t * 8 + 4] = o1;
        }
    }
}

// ---- K5: GCN edge aggregation: g1[t] += xW[s] * norm -----------------------
__global__ void __launch_bounds__(256) k_edge_gcn(
    const float* __restrict__ attr, const int* __restrict__ eid,
    const int* __restrict__ src, const int* __restrict__ tgt, int E, int n2) {
    int e = blockIdx.x * 8 + (threadIdx.x >> 5);
    if (e >= E) return;
    int lane = threadIdx.x & 31;
    int s = 0, t = 0; float w = 0.f;
    if (lane == 0) {
        s = __ldg(&src[e]);
        t = __ldg(&tgt[e]);
        w = __ldg(&attr[__ldg(&eid[e])]);
    }
    s = __shfl_sync(0xffffffffu, s, 0);
    t = __shfl_sync(0xffffffffu, t, 0);
    w = __shfl_sync(0xffffffffu, w, 0);
    if (t >= n2) return;   // defensive; setup guarantees t < n2
    float ds = (s < n2) ? g_dinv[s] : 1.f;
    float nm = ds * w * g_dinv[t];
    const float4 v = *(const float4*)&g_xW[(size_t)s * H + lane * 4];
    float* dst = &g_g1[(size_t)t * H + lane * 4];
    asm volatile("red.global.add.v4.f32 [%0], {%1, %2, %3, %4};"
                 :: "l"(dst), "f"(v.x * nm), "f"(v.y * nm),
                    "f"(v.z * nm), "f"(v.w * nm)
                 : "memory");
}

// ---- K6: finalize g1 = agg + xW*dinv^2 + b  (rows < n1) --------------------
__global__ void k_fin_g1(const float* __restrict__ b, const int* __restrict__ n1p,
                         int N0, int n2) {
    int n1 = clamp_n1(n1p, N0);
    int idx4 = blockIdx.x * blockDim.x + threadIdx.x;  // float4 index
    int i = idx4 >> 5;
    if (i >= n1) return;
    int j4 = idx4 & 31;
    size_t off = (size_t)i * H + j4 * 4;
    float4 xw = *(const float4*)&g_xW[off];
    float4 bb = *(const float4*)&b[j4 * 4];
    float4 o;
    if (i < n2) {
        float di = g_dinv[i];
        float d2 = di * di;
        float4 g = *(const float4*)&g_g1[off];
        o.x = g.x + xw.x * d2 + bb.x;
        o.y = g.y + xw.y * d2 + bb.y;
        o.z = g.z + xw.z * d2 + bb.z;
        o.w = g.w + xw.w * d2 + bb.w;
    } else {
        o.x = xw.x + bb.x;
        o.y = xw.y + bb.y;
        o.z = xw.z + bb.z;
        o.w = xw.w + bb.w;
    }
    *(float4*)&g_g1[off] = o;
}

// ---- K7: SAGE sum: s[t] += g1[src] -----------------------------------------
__global__ void __launch_bounds__(256) k_edge_sage(
    const int* __restrict__ src, const int* __restrict__ tgt, int E, int n2) {
    int e = blockIdx.x * 8 + (threadIdx.x >> 5);
    if (e >= E) return;
    int lane = threadIdx.x & 31;
    int s = 0, t = 0;
    if (lane == 0) { s = __ldg(&src[e]); t = __ldg(&tgt[e]); }
    s = __shfl_sync(0xffffffffu, s, 0);
    t = __shfl_sync(0xffffffffu, t, 0);
    if (t >= n2) return;
    const float4 v = *(const float4*)&g_g1[(size_t)s * H + lane * 4];
    float* dst = &g_s[(size_t)t * H + lane * 4];
    asm volatile("red.global.add.v4.f32 [%0], {%1, %2, %3, %4};"
                 :: "l"(dst), "f"(v.x), "f"(v.y), "f"(v.z), "f"(v.w)
                 : "memory");
}

// ---- K8: out = l2norm( mean @ Wl^T + bl + g1 @ Wr^T ) ----------------------
__global__ void __launch_bounds__(256) k_sage_out(
    const float* __restrict__ Wl, const float* __restrict__ bl,
    const float* __restrict__ Wr, int n2, float* __restrict__ out) {
    extern __shared__ float sm[];
    float* Wlt  = sm;                      // H*SW
    float* Wrt  = Wlt  + H * SW;           // H*SW
    float* ms   = Wrt  + H * SW;           // H*SX  (mean, transposed)
    float* gs   = ms   + H * SX;           // H*SX  (g1, transposed)
    float* rc   = gs   + H * SX;           // GROWS
    float* psum = rc   + GROWS;            // GROWS*16
    float* scl  = psum + GROWS * 16;       // GROWS

    int row0 = blockIdx.x * GROWS;
    int tid = threadIdx.x;

    for (int idx = tid; idx < H * H; idx += 256) {
        int j = idx >> 7, k = idx & 127;
        Wlt[k * SW + j] = Wl[idx];
        Wrt[k * SW + j] = Wr[idx];
    }
    if (tid < GROWS) {
        int row = row0 + tid;
        float c = (row < n2) ? g_cnt[row] : 1.f;
        rc[tid] = 1.f / fmaxf(c, 1.f);
    }
    __syncthreads();
    for (int idx = tid; idx < GROWS * H; idx += 256) {
        int r = idx >> 7, k = idx & 127;
        int row = row0 + r;
        if (row < n2) {
            size_t off = (size_t)row * H + k;
            ms[k * SX + r] = g_s[off] * rc[r];
            gs[k * SX + r] = g_g1[off];
        } else {
            ms[k * SX + r] = 0.f;
            gs[k * SX + r] = 0.f;
        }
    }
    __syncthreads();

    int col_t = tid & 15;
    int row_t = tid >> 4;
    float acc[4][8];
#pragma unroll
    for (int j = 0; j < 8; ++j) {
        float bv = bl[col_t * 8 + j];
#pragma unroll
        for (int i = 0; i < 4; ++i) acc[i][j] = bv;
    }

    for (int k = 0; k < H; ++k) {
        float4 am4 = *(const float4*)&ms[k * SX + row_t * 4];
        float4 ag4 = *(const float4*)&gs[k * SX + row_t * 4];
        float4 l0 = *(const float4*)&Wlt[k * SW + col_t * 8];
        float4 l1 = *(const float4*)&Wlt[k * SW + col_t * 8 + 4];
        float4 r0 = *(const float4*)&Wrt[k * SW + col_t * 8];
        float4 r1 = *(const float4*)&Wrt[k * SW + col_t * 8 + 4];
        float am[4] = {am4.x, am4.y, am4.z, am4.w};
        float ag[4] = {ag4.x, ag4.y, ag4.z, ag4.w};
        float wl[8] = {l0.x, l0.y, l0.z, l0.w, l1.x, l1.y, l1.z, l1.w};
        float wr[8] = {r0.x, r0.y, r0.z, r0.w, r1.x, r1.y, r1.z, r1.w};
#pragma unroll
        for (int i = 0; i < 4; ++i)
#pragma unroll
            for (int j = 0; j < 8; ++j)
                acc[i][j] += am[i] * wl[j] + ag[i] * wr[j];
    }

    // row-wise L2 norm across the 16 col-thread groups
#pragma unroll
    for (int i = 0; i < 4; ++i) {
        float loc = 0.f;
#pragma unroll
        for (int j = 0; j < 8; ++j) loc += acc[i][j] * acc[i][j];
        psum[(row_t * 4 + i) * 16 + col_t] = loc;
    }
    __syncthreads();
    if (tid < GROWS) {
        float ssum = 0.f;
#pragma unroll
        for (int c = 0; c < 16; ++c) ssum += psum[tid * 16 + c];
        scl[tid] = 1.f / fmaxf(sqrtf(ssum), 1e-12f);
    }
    __syncthreads();

#pragma unroll
    for (int i = 0; i < 4; ++i) {
        int row = row0 + row_t * 4 + i;
        if (row < n2) {
            float sc = scl[row_t * 4 + i];
            float4 o0 = make_float4(acc[i][0] * sc, acc[i][1] * sc,
                                    acc[i][2] * sc, acc[i][3] * sc);
            float4 o1 = make_float4(acc[i][4] * sc, acc[i][5] * sc,
                                    acc[i][6] * sc, acc[i][7] * sc);
            *(float4*)&out[(size_t)row * H + col_t * 8]     = o0;
            *(float4*)&out[(size_t)row * H + col_t * 8 + 4] = o1;
        }
    }
}

// ---------------------------------------------------------------------------
extern "C" void kernel_launch(void* const* d_in, const int* in_sizes, int n_in,
                              void* d_out, int out_size) {
    const float* x     = (const float*)d_in[0];
    const float* attr  = (const float*)d_in[1];
    const int*   e_id1 = (const int*)d_in[3];
    const int*   src1  = (const int*)d_in[6];
    const int*   tgt1  = (const int*)d_in[7];
    const int*   n1p   = (const int*)d_in[8];
    const float* gcn_W = (const float*)d_in[10];
    const float* gcn_b = (const float*)d_in[11];
    const float* Wl1   = (const float*)d_in[15];
    const float* bl1   = (const float*)d_in[16];
    const float* Wr1   = (const float*)d_in[17];
    float* out = (float*)d_out;

    int N0 = in_sizes[0] / H;  if (N0 > MAXN0) N0 = MAXN0;
    int E1 = in_sizes[3];
    int n2 = out_size / H;     if (n2 > MAXN2) n2 = MAXN2;

    constexpr int SMEM_K4 = (H * SW + H * SX) * 4;
    constexpr int SMEM_K8 = (2 * H * SW + 2 * H * SX + GROWS + GROWS * 16 + GROWS) * 4;
    cudaFuncSetAttribute(k_gemm_xw, cudaFuncAttributeMaxDynamicSharedMemorySize, SMEM_K4);
    cudaFuncSetAttribute(k_sage_out, cudaFuncAttributeMaxDynamicSharedMemorySize, SMEM_K8);

    k_init<<<(n2 * H + 255) / 256, 256>>>(n2);
    k_degcnt<<<(E1 + 255) / 256, 256>>>(attr, e_id1, tgt1, E1, n2);
    k_dinv<<<(n2 + 255) / 256, 256>>>(n2);
    k_gemm_xw<<<(N0 + GROWS - 1) / GROWS, 256, SMEM_K4>>>(x, gcn_W, n1p, N0);
    k_edge_gcn<<<(E1 + 7) / 8, 256>>>(attr, e_id1, src1, tgt1, E1, n2);
    k_fin_g1<<<(N0 * 32 + 255) / 256, 256>>>(gcn_b, n1p, N0, n2);
    k_edge_sage<<<(E1 + 7) / 8, 256>>>(src1, tgt1, E1, n2);
    k_sage_out<<<(n2 + GROWS - 1) / GROWS, 256, SMEM_K8>>>(Wl1, bl1, Wr1, n2, out);
}

// round 2
// speedup vs baseline: 1.4064x; 1.4064x over previous
#include <cuda_runtime.h>
#include <cstdint>

// ---------------------------------------------------------------------------
// GlobalGNN layer-1-only pipeline:
//   xW   = x @ gcn_W^T                       (tf32 tensor-core GEMM, 3-term split)
//   CSR build over (src1,tgt1) with per-edge norm = dinv[s]*w*dinv[t]
//   g1[t<n2]  = gather(norm * xW[src]) + xW[t]*dinv[t]^2 + b
//   g1[n2..n1)= xW + b
//   mean[t]   = gather(g1[src]) / max(cnt,1)
//   out = l2norm( mean @ Wl1^T + bl1 + g1[:n2] @ Wr1^T )
// ---------------------------------------------------------------------------

#define H 128
#define MAXN0 131072
#define MAXN2 16384
#define MAXE  1048576
#define GROWS 64
#define SW 132
#define SX 68
#define XST 72   // padded smem stride (floats) for GEMM tiles, 16B-aligned

__device__ __align__(16) float g_xW[(size_t)MAXN0 * H];
__device__ __align__(16) float g_g1[(size_t)MAXN0 * H];
__device__ __align__(16) float g_s [(size_t)MAXN2 * H];
__device__ float g_deg [MAXN2];
__device__ float g_dinv[MAXN2];
__device__ int   g_hist[MAXN2];
__device__ int   g_cur [MAXN2];
__device__ int   g_off [MAXN2 + 1];
__device__ int   g_esrc[MAXE];
__device__ float g_ew  [MAXE];

__device__ __forceinline__ int clamp_n1(const int* p, int N0) {
    int v = *p;
    if (v <= 0 || v > N0) v = N0;
    return v;
}

__device__ __forceinline__ void tf32split(float f, uint32_t& hi, uint32_t& lo) {
    uint32_t h;
    asm("cvt.rna.tf32.f32 %0, %1;" : "=r"(h) : "f"(f));
    float r = f - __uint_as_float(h);
    asm("cvt.rna.tf32.f32 %0, %1;" : "=r"(lo) : "f"(r));
    hi = h;
}

#define MMA(d, a0, a1, a2, a3, b0, b1)                                        \
    asm volatile(                                                             \
        "mma.sync.aligned.m16n8k8.row.col.f32.tf32.tf32.f32 "                 \
        "{%0,%1,%2,%3},{%4,%5,%6,%7},{%8,%9},{%0,%1,%2,%3};"                  \
        : "+f"(d[0]), "+f"(d[1]), "+f"(d[2]), "+f"(d[3])                      \
        : "r"(a0), "r"(a1), "r"(a2), "r"(a3), "r"(b0), "r"(b1))

// ---- K1: init per-target scratch -------------------------------------------
__global__ void k_init(int n2) {
    int i = blockIdx.x * blockDim.x + threadIdx.x;
    if (i < n2) { g_deg[i] = 1.f; g_hist[i] = 0; g_cur[i] = 0; }
}

// ---- K2: histogram + weighted degree ----------------------------------------
__global__ void k_hist(const float* __restrict__ attr, const int* __restrict__ eid,
                       const int* __restrict__ tgt, int E, int n2) {
    int e = blockIdx.x * blockDim.x + threadIdx.x;
    if (e >= E) return;
    int t = __ldg(&tgt[e]);
    if (t >= n2) return;
    atomicAdd(&g_hist[t], 1);
    atomicAdd(&g_deg[t], __ldg(&attr[__ldg(&eid[e])]));
}

// ---- K3: dinv ----------------------------------------------------------------
__global__ void k_dinv(int n2) {
    int i = blockIdx.x * blockDim.x + threadIdx.x;
    if (i < n2) g_dinv[i] = rsqrtf(g_deg[i]);
}

// ---- K4: exclusive scan (single block, n2 <= 16384) ---------------------------
__global__ void __launch_bounds__(1024) k_scan(int n2) {
    __shared__ int sums[1024];
    int tid = threadIdx.x;
    int base = tid * 16;
    int vals[16];
    int local = 0;
#pragma unroll
    for (int i = 0; i < 16; ++i) {
        int idx = base + i;
        int v = (idx < n2) ? g_hist[idx] : 0;
        vals[i] = local;
        local += v;
    }
    sums[tid] = local;
    __syncthreads();
    for (int off = 1; off < 1024; off <<= 1) {
        int v = (tid >= off) ? sums[tid - off] : 0;
        __syncthreads();
        sums[tid] += v;
        __syncthreads();
    }
    int prev = (tid == 0) ? 0 : sums[tid - 1];
#pragma unroll
    for (int i = 0; i < 16; ++i) {
        int idx = base + i;
        if (idx < n2) g_off[idx] = prev + vals[i];
    }
    if (tid == 1023) g_off[n2] = sums[1023];
}

// ---- K5: scatter edges into CSR, precompute norm ------------------------------
__global__ void k_scatter(const float* __restrict__ attr, const int* __restrict__ eid,
                          const int* __restrict__ src, const int* __restrict__ tgt,
                          int E, int n2) {
    int e = blockIdx.x * blockDim.x + threadIdx.x;
    if (e >= E) return;
    int t = __ldg(&tgt[e]);
    if (t >= n2) return;
    int pos = g_off[t] + atomicAdd(&g_cur[t], 1);
    int s = __ldg(&src[e]);
    float w = __ldg(&attr[__ldg(&eid[e])]);
    float ds = (s < n2) ? g_dinv[s] : 1.f;
    g_esrc[pos] = s;
    g_ew[pos] = ds * w * g_dinv[t];
}

// ---- K6: xW = x @ W^T via tf32 tensor cores (rows < n1) -----------------------
__global__ void __launch_bounds__(256) k_gemm_tc(
    const float* __restrict__ x, const float* __restrict__ W,
    const int* __restrict__ n1p, int N0) {
    extern __shared__ float sm[];
    float* xs = sm;                 // [128][XST]
    float* ws = sm + 128 * XST;     // [128][XST]

    int n1 = clamp_n1(n1p, N0);
    int row0 = blockIdx.x * 128;
    if (row0 >= n1) return;

    int tid = threadIdx.x, lane = tid & 31, warp = tid >> 5;
    int wm = warp >> 1;   // 0..3 -> 32-row slab
    int wn = warp & 1;    // 0..1 -> 64-col slab
    int lq = lane >> 2;   // 0..7
    int lr = lane & 3;    // 0..3

    float acc[2][8][4];
#pragma unroll
    for (int mi = 0; mi < 2; ++mi)
#pragma unroll
        for (int ni = 0; ni < 8; ++ni)
#pragma unroll
            for (int j = 0; j < 4; ++j) acc[mi][ni][j] = 0.f;

    for (int kc = 0; kc < H; kc += 64) {
        if (kc) __syncthreads();
#pragma unroll
        for (int it = 0; it < 8; ++it) {
            int f4 = it * 256 + tid;
            int r = f4 >> 4, k4 = f4 & 15;
            int row = row0 + r;
            float4 v = make_float4(0.f, 0.f, 0.f, 0.f);
            if (row < N0) v = *(const float4*)&x[(size_t)row * H + kc + k4 * 4];
            *(float4*)&xs[r * XST + k4 * 4] = v;
            float4 wv = *(const float4*)&W[(size_t)r * H + kc + k4 * 4];
            *(float4*)&ws[r * XST + k4 * 4] = wv;
        }
        __syncthreads();

#pragma unroll
        for (int ks = 0; ks < 8; ++ks) {
            int kb = ks * 8 + lr;
            uint32_t ah[2][4], al[2][4];
#pragma unroll
            for (int mi = 0; mi < 2; ++mi) {
                int r = wm * 32 + mi * 16 + lq;
                float a0 = xs[r * XST + kb];
                float a1 = xs[(r + 8) * XST + kb];
                float a2 = xs[r * XST + kb + 4];
                float a3 = xs[(r + 8) * XST + kb + 4];
                tf32split(a0, ah[mi][0], al[mi][0]);
                tf32split(a1, ah[mi][1], al[mi][1]);
                tf32split(a2, ah[mi][2], al[mi][2]);
                tf32split(a3, ah[mi][3], al[mi][3]);
            }
#pragma unroll
            for (int ni = 0; ni < 8; ++ni) {
                int n = wn * 64 + ni * 8 + lq;
                float b0 = ws[n * XST + kb];
                float b1 = ws[n * XST + kb + 4];
                uint32_t bh0, bl0, bh1, bl1;
                tf32split(b0, bh0, bl0);
                tf32split(b1, bh1, bl1);
#pragma unroll
                for (int mi = 0; mi < 2; ++mi) {
                    MMA(acc[mi][ni], ah[mi][0], ah[mi][1], ah[mi][2], ah[mi][3], bh0, bh1);
                    MMA(acc[mi][ni], ah[mi][0], ah[mi][1], ah[mi][2], ah[mi][3], bl0, bl1);
                    MMA(acc[mi][ni], al[mi][0], al[mi][1], al[mi][2], al[mi][3], bh0, bh1);
                }
            }
        }
    }

#pragma unroll
    for (int mi = 0; mi < 2; ++mi) {
        int r0 = row0 + wm * 32 + mi * 16 + lq;
#pragma unroll
        for (int ni = 0; ni < 8; ++ni) {
            int col = wn * 64 + ni * 8 + lr * 2;
            if (r0 < n1) {
                float2 v0 = make_float2(acc[mi][ni][0], acc[mi][ni][1]);
                *(float2*)&g_xW[(size_t)r0 * H + col] = v0;
            }
            int r1 = r0 + 8;
            if (r1 < n1) {
                float2 v1 = make_float2(acc[mi][ni][2], acc[mi][ni][3]);
                *(float2*)&g_xW[(size_t)r1 * H + col] = v1;
            }
        }
    }
}

// ---- K7: GCN gather: g1[t<n2] = sum(norm*xW[s]) + xW[t]*dinv^2 + b ------------
__global__ void __launch_bounds__(256) k_gather_gcn(
    const float* __restrict__ b, int n2) {
    int warp = threadIdx.x >> 5;
    int t = blockIdx.x * 8 + warp;
    if (t >= n2) return;
    int lane = threadIdx.x & 31;
    int c4 = lane * 4;
    int base = __ldg(&g_off[t]);
    int end  = __ldg(&g_off[t + 1]);

    float4 acc = make_float4(0.f, 0.f, 0.f, 0.f);
    int i = base;
    for (; i + 2 <= end; i += 2) {
        int   s0 = __ldg(&g_esrc[i]);
        float w0 = __ldg(&g_ew[i]);
        int   s1 = __ldg(&g_esrc[i + 1]);
        float w1 = __ldg(&g_ew[i + 1]);
        float4 v0 = *(const float4*)&g_xW[(size_t)s0 * H + c4];
        float4 v1 = *(const float4*)&g_xW[(size_t)s1 * H + c4];
        acc.x += w0 * v0.x + w1 * v1.x;
        acc.y += w0 * v0.y + w1 * v1.y;
        acc.z += w0 * v0.z + w1 * v1.z;
        acc.w += w0 * v0.w + w1 * v1.w;
    }
    if (i < end) {
        int   s0 = __ldg(&g_esrc[i]);
        float w0 = __ldg(&g_ew[i]);
        float4 v0 = *(const float4*)&g_xW[(size_t)s0 * H + c4];
        acc.x += w0 * v0.x;
        acc.y += w0 * v0.y;
        acc.z += w0 * v0.z;
        acc.w += w0 * v0.w;
    }
    float di = g_dinv[t];
    float d2 = di * di;
    float4 xw = *(const float4*)&g_xW[(size_t)t * H + c4];
    float4 bb = *(const float4*)&b[c4];
    acc.x += xw.x * d2 + bb.x;
    acc.y += xw.y * d2 + bb.y;
    acc.z += xw.z * d2 + bb.z;
    acc.w += xw.w * d2 + bb.w;
    *(float4*)&g_g1[(size_t)t * H + c4] = acc;
}

// ---- K8: g1[n2..n1) = xW + b ---------------------------------------------------
__global__ void k_fin_tail(const float* __restrict__ b, const int* __restrict__ n1p,
                           int N0, int n2) {
    int n1 = clamp_n1(n1p, N0);
    int idx4 = blockIdx.x * blockDim.x + threadIdx.x;
    int i = n2 + (idx4 >> 5);
    if (i >= n1) return;
    int j4 = idx4 & 31;
    size_t off = (size_t)i * H + j4 * 4;
    float4 xw = *(const float4*)&g_xW[off];
    float4 bb = *(const float4*)&b[j4 * 4];
    xw.x += bb.x; xw.y += bb.y; xw.z += bb.z; xw.w += bb.w;
    *(float4*)&g_g1[off] = xw;
}

// ---- K9: SAGE gather: s[t] = mean(g1[src]) -------------------------------------
__global__ void __launch_bounds__(256) k_gather_sage(int n2) {
    int warp = threadIdx.x >> 5;
    int t = blockIdx.x * 8 + warp;
    if (t >= n2) return;
    int lane = threadIdx.x & 31;
    int c4 = lane * 4;
    int base = __ldg(&g_off[t]);
    int end  = __ldg(&g_off[t + 1]);

    float4 acc = make_float4(0.f, 0.f, 0.f, 0.f);
    int i = base;
    for (; i + 2 <= end; i += 2) {
        int s0 = __ldg(&g_esrc[i]);
        int s1 = __ldg(&g_esrc[i + 1]);
        float4 v0 = *(const float4*)&g_g1[(size_t)s0 * H + c4];
        float4 v1 = *(const float4*)&g_g1[(size_t)s1 * H + c4];
        acc.x += v0.x + v1.x;
        acc.y += v0.y + v1.y;
        acc.z += v0.z + v1.z;
        acc.w += v0.w + v1.w;
    }
    if (i < end) {
        int s0 = __ldg(&g_esrc[i]);
        float4 v0 = *(const float4*)&g_g1[(size_t)s0 * H + c4];
        acc.x += v0.x; acc.y += v0.y; acc.z += v0.z; acc.w += v0.w;
    }
    float inv = 1.f / fmaxf((float)(end - base), 1.f);
    acc.x *= inv; acc.y *= inv; acc.z *= inv; acc.w *= inv;
    *(float4*)&g_s[(size_t)t * H + c4] = acc;
}

// ---- K10: out = l2norm( mean @ Wl^T + bl + g1 @ Wr^T ) --------------------------
__global__ void __launch_bounds__(256) k_sage_out(
    const float* __restrict__ Wl, const float* __restrict__ bl,
    const float* __restrict__ Wr, int n2, float* __restrict__ out) {
    extern __shared__ float sm[];
    float* Wlt  = sm;
    float* Wrt  = Wlt + H * SW;
    float* ms   = Wrt + H * SW;
    float* gs   = ms  + H * SX;
    float* psum = gs  + H * SX;
    float* scl  = psum + GROWS * 16;

    int row0 = blockIdx.x * GROWS;
    int tid = threadIdx.x;

    for (int idx = tid; idx < H * H; idx += 256) {
        int j = idx >> 7, k = idx & 127;
        Wlt[k * SW + j] = Wl[idx];
        Wrt[k * SW + j] = Wr[idx];
    }
    for (int idx = tid; idx < GROWS * H; idx += 256) {
        int r = idx >> 7, k = idx & 127;
        int row = row0 + r;
        if (row < n2) {
            size_t off = (size_t)row * H + k;
            ms[k * SX + r] = g_s[off];
            gs[k * SX + r] = g_g1[off];
        } else {
            ms[k * SX + r] = 0.f;
            gs[k * SX + r] = 0.f;
        }
    }
    __syncthreads();

    int col_t = tid & 15;
    int row_t = tid >> 4;
    float acc[4][8];
#pragma unroll
    for (int j = 0; j < 8; ++j) {
        float bv = bl[col_t * 8 + j];
#pragma unroll
        for (int i = 0; i < 4; ++i) acc[i][j] = bv;
    }

    for (int k = 0; k < H; ++k) {
        float4 am4 = *(const float4*)&ms[k * SX + row_t * 4];
        float4 ag4 = *(const float4*)&gs[k * SX + row_t * 4];
        float4 l0 = *(const float4*)&Wlt[k * SW + col_t * 8];
        float4 l1 = *(const float4*)&Wlt[k * SW + col_t * 8 + 4];
        float4 r0 = *(const float4*)&Wrt[k * SW + col_t * 8];
        float4 r1 = *(const float4*)&Wrt[k * SW + col_t * 8 + 4];
        float am[4] = {am4.x, am4.y, am4.z, am4.w};
        float ag[4] = {ag4.x, ag4.y, ag4.z, ag4.w};
        float wl[8] = {l0.x, l0.y, l0.z, l0.w, l1.x, l1.y, l1.z, l1.w};
        float wr[8] = {r0.x, r0.y, r0.z, r0.w, r1.x, r1.y, r1.z, r1.w};
#pragma unroll
        for (int i = 0; i < 4; ++i)
#pragma unroll
            for (int j = 0; j < 8; ++j)
                acc[i][j] += am[i] * wl[j] + ag[i] * wr[j];
    }

#pragma unroll
    for (int i = 0; i < 4; ++i) {
        float loc = 0.f;
#pragma unroll
        for (int j = 0; j < 8; ++j) loc += acc[i][j] * acc[i][j];
        psum[(row_t * 4 + i) * 16 + col_t] = loc;
    }
    __syncthreads();
    if (tid < GROWS) {
        float ssum = 0.f;
#pragma unroll
        for (int c = 0; c < 16; ++c) ssum += psum[tid * 16 + c];
        scl[tid] = 1.f / fmaxf(sqrtf(ssum), 1e-12f);
    }
    __syncthreads();

#pragma unroll
    for (int i = 0; i < 4; ++i) {
        int row = row0 + row_t * 4 + i;
        if (row < n2) {
            float sc = scl[row_t * 4 + i];
            float4 o0 = make_float4(acc[i][0] * sc, acc[i][1] * sc,
                                    acc[i][2] * sc, acc[i][3] * sc);
            float4 o1 = make_float4(acc[i][4] * sc, acc[i][5] * sc,
                                    acc[i][6] * sc, acc[i][7] * sc);
            *(float4*)&out[(size_t)row * H + col_t * 8]     = o0;
            *(float4*)&out[(size_t)row * H + col_t * 8 + 4] = o1;
        }
    }
}

// ---------------------------------------------------------------------------
extern "C" void kernel_launch(void* const* d_in, const int* in_sizes, int n_in,
                              void* d_out, int out_size) {
    const float* x     = (const float*)d_in[0];
    const float* attr  = (const float*)d_in[1];
    const int*   e_id1 = (const int*)d_in[3];
    const int*   src1  = (const int*)d_in[6];
    const int*   tgt1  = (const int*)d_in[7];
    const int*   n1p   = (const int*)d_in[8];
    const float* gcn_W = (const float*)d_in[10];
    const float* gcn_b = (const float*)d_in[11];
    const float* Wl1   = (const float*)d_in[15];
    const float* bl1   = (const float*)d_in[16];
    const float* Wr1   = (const float*)d_in[17];
    float* out = (float*)d_out;

    int N0 = in_sizes[0] / H;  if (N0 > MAXN0) N0 = MAXN0;
    int E1 = in_sizes[3];      if (E1 > MAXE)  E1 = MAXE;
    int n2 = out_size / H;     if (n2 > MAXN2) n2 = MAXN2;

    constexpr int SMEM_GEMM = 128 * XST * 2 * 4;
    constexpr int SMEM_K10 = (2 * H * SW + 2 * H * SX + GROWS * 16 + GROWS) * 4;
    cudaFuncSetAttribute(k_gemm_tc, cudaFuncAttributeMaxDynamicSharedMemorySize, SMEM_GEMM);
    cudaFuncSetAttribute(k_sage_out, cudaFuncAttributeMaxDynamicSharedMemorySize, SMEM_K10);

    k_init<<<(n2 + 255) / 256, 256>>>(n2);
    k_hist<<<(E1 + 255) / 256, 256>>>(attr, e_id1, tgt1, E1, n2);
    k_dinv<<<(n2 + 255) / 256, 256>>>(n2);
    k_scan<<<1, 1024>>>(n2);
    k_scatter<<<(E1 + 255) / 256, 256>>>(attr, e_id1, src1, tgt1, E1, n2);
    k_gemm_tc<<<(N0 + 127) / 128, 256, SMEM_GEMM>>>(x, gcn_W, n1p, N0);
    k_gather_gcn<<<(n2 + 7) / 8, 256>>>(gcn_b, n2);
    k_fin_tail<<<(N0 * 32 + 255) / 256, 256>>>(gcn_b, n1p, N0, n2);
    k_gather_sage<<<(n2 + 7) / 8, 256>>>(n2);
    k_sage_out<<<(n2 + GROWS - 1) / GROWS, 256, SMEM_K10>>>(Wl1, bl1, Wr1, n2, out);
}

// round 3
// speedup vs baseline: 1.5958x; 1.1347x over previous
#include <cuda_runtime.h>
#include <cstdint>

// ---------------------------------------------------------------------------
// GlobalGNN layer-1-only pipeline (see round 1/2 derivation):
//   xW   = x @ gcn_W^T   (tf32 TC GEMM, 3-term split)   [stream 2, overlapped]
//   CSR build over (src1,tgt1) with per-edge norm                [stream 1]
//   g1[t<n2]  = gather(norm * xW[src]) + xW[t]*dinv^2 + b ; g1[n2..n1)=xW+b
//   mean[t]   = gather(g1[src]) / max(cnt,1)
//   out = l2norm( mean @ Wl1^T + bl1 + g1[:n2] @ Wr1^T )
// ---------------------------------------------------------------------------

#define H 128
#define MAXN0 131072
#define MAXN2 16384
#define MAXE  1048576
#define GROWS 64
#define SW 132
#define SX 68
#define XST 72

__device__ __align__(16) float g_xW[(size_t)MAXN0 * H];
__device__ __align__(16) float g_g1[(size_t)MAXN0 * H];
__device__ __align__(16) float g_s [(size_t)MAXN2 * H];
__device__ float g_deg [MAXN2];
__device__ float g_dinv[MAXN2];
__device__ int   g_hist[MAXN2];
__device__ int   g_cur [MAXN2];
__device__ int   g_off [MAXN2 + 1];
__device__ int   g_esrc[MAXE];
__device__ float g_ew  [MAXE];

__device__ __forceinline__ int clamp_n1(const int* p, int N0) {
    int v = *p;
    if (v <= 0 || v > N0) v = N0;
    return v;
}

__device__ __forceinline__ void tf32split(float f, uint32_t& hi, uint32_t& lo) {
    uint32_t h;
    asm("cvt.rna.tf32.f32 %0, %1;" : "=r"(h) : "f"(f));
    float r = f - __uint_as_float(h);
    asm("cvt.rna.tf32.f32 %0, %1;" : "=r"(lo) : "f"(r));
    hi = h;
}

#define MMA(d, a0, a1, a2, a3, b0, b1)                                        \
    asm volatile(                                                             \
        "mma.sync.aligned.m16n8k8.row.col.f32.tf32.tf32.f32 "                 \
        "{%0,%1,%2,%3},{%4,%5,%6,%7},{%8,%9},{%0,%1,%2,%3};"                  \
        : "+f"(d[0]), "+f"(d[1]), "+f"(d[2]), "+f"(d[3])                      \
        : "r"(a0), "r"(a1), "r"(a2), "r"(a3), "r"(b0), "r"(b1))

// ---- K1: init per-target scratch -------------------------------------------
__global__ void k_init(int n2) {
    int i = blockIdx.x * blockDim.x + threadIdx.x;
    if (i < n2) { g_deg[i] = 1.f; g_hist[i] = 0; g_cur[i] = 0; }
}

// ---- K2: histogram + weighted degree ----------------------------------------
__global__ void k_hist(const float* __restrict__ attr, const int* __restrict__ eid,
                       const int* __restrict__ tgt, int E, int n2) {
    int e = blockIdx.x * blockDim.x + threadIdx.x;
    if (e >= E) return;
    int t = __ldg(&tgt[e]);
    if (t >= n2) return;
    atomicAdd(&g_hist[t], 1);
    atomicAdd(&g_deg[t], __ldg(&attr[__ldg(&eid[e])]));
}

// ---- K3: warp-shuffle exclusive scan (+fused dinv), single block --------------
__global__ void __launch_bounds__(1024) k_scan_dinv(int n2) {
    __shared__ int wsum[32];
    int tid = threadIdx.x, lane = tid & 31, wid = tid >> 5;
    int base = tid * 16;
    int vals[16];
    int local = 0;
#pragma unroll
    for (int i = 0; i < 16; ++i) {
        int idx = base + i;
        int h = (idx < n2) ? g_hist[idx] : 0;
        vals[i] = local;
        local += h;
    }
    // inclusive warp scan of per-thread totals
    int inc = local;
#pragma unroll
    for (int off = 1; off < 32; off <<= 1) {
        int nb = __shfl_up_sync(0xffffffffu, inc, off);
        if (lane >= off) inc += nb;
    }
    if (lane == 31) wsum[wid] = inc;
    __syncthreads();
    if (wid == 0) {
        int s = wsum[lane];
#pragma unroll
        for (int off = 1; off < 32; off <<= 1) {
            int nb = __shfl_up_sync(0xffffffffu, s, off);
            if (lane >= off) s += nb;
        }
        wsum[lane] = s;
    }
    __syncthreads();
    int wbase = (wid > 0) ? wsum[wid - 1] : 0;
    int excl = wbase + inc - local;
#pragma unroll
    for (int i = 0; i < 16; ++i) {
        int idx = base + i;
        if (idx < n2) g_off[idx] = excl + vals[i];
    }
    if (tid == 1023) g_off[n2] = wsum[31];
    // fused dinv
    for (int i = tid; i < n2; i += 1024) g_dinv[i] = rsqrtf(g_deg[i]);
}

// ---- K4: scatter edges into CSR, precompute norm ------------------------------
__global__ void k_scatter(const float* __restrict__ attr, const int* __restrict__ eid,
                          const int* __restrict__ src, const int* __restrict__ tgt,
                          int E, int n2) {
    int e = blockIdx.x * blockDim.x + threadIdx.x;
    if (e >= E) return;
    int t = __ldg(&tgt[e]);
    if (t >= n2) return;
    int pos = g_off[t] + atomicAdd(&g_cur[t], 1);
    int s = __ldg(&src[e]);
    float w = __ldg(&attr[__ldg(&eid[e])]);
    float ds = (s < n2) ? g_dinv[s] : 1.f;
    g_esrc[pos] = s;
    g_ew[pos] = ds * w * g_dinv[t];
}

// ---- K5: xW = x @ W^T via tf32 tensor cores (rows < n1) -----------------------
__global__ void __launch_bounds__(256) k_gemm_tc(
    const float* __restrict__ x, const float* __restrict__ W,
    const int* __restrict__ n1p, int N0) {
    extern __shared__ float sm[];
    float* xs = sm;
    float* ws = sm + 128 * XST;

    int n1 = clamp_n1(n1p, N0);
    int row0 = blockIdx.x * 128;
    if (row0 >= n1) return;

    int tid = threadIdx.x, lane = tid & 31, warp = tid >> 5;
    int wm = warp >> 1;
    int wn = warp & 1;
    int lq = lane >> 2;
    int lr = lane & 3;

    float acc[2][8][4];
#pragma unroll
    for (int mi = 0; mi < 2; ++mi)
#pragma unroll
        for (int ni = 0; ni < 8; ++ni)
#pragma unroll
            for (int j = 0; j < 4; ++j) acc[mi][ni][j] = 0.f;

    for (int kc = 0; kc < H; kc += 64) {
        if (kc) __syncthreads();
#pragma unroll
        for (int it = 0; it < 8; ++it) {
            int f4 = it * 256 + tid;
            int r = f4 >> 4, k4 = f4 & 15;
            int row = row0 + r;
            float4 v = make_float4(0.f, 0.f, 0.f, 0.f);
            if (row < N0) v = *(const float4*)&x[(size_t)row * H + kc + k4 * 4];
            *(float4*)&xs[r * XST + k4 * 4] = v;
            float4 wv = *(const float4*)&W[(size_t)r * H + kc + k4 * 4];
            *(float4*)&ws[r * XST + k4 * 4] = wv;
        }
        __syncthreads();

#pragma unroll
        for (int ks = 0; ks < 8; ++ks) {
            int kb = ks * 8 + lr;
            uint32_t ah[2][4], al[2][4];
#pragma unroll
            for (int mi = 0; mi < 2; ++mi) {
                int r = wm * 32 + mi * 16 + lq;
                tf32split(xs[r * XST + kb],       ah[mi][0], al[mi][0]);
                tf32split(xs[(r + 8) * XST + kb], ah[mi][1], al[mi][1]);
                tf32split(xs[r * XST + kb + 4],       ah[mi][2], al[mi][2]);
                tf32split(xs[(r + 8) * XST + kb + 4], ah[mi][3], al[mi][3]);
            }
#pragma unroll
            for (int ni = 0; ni < 8; ++ni) {
                int n = wn * 64 + ni * 8 + lq;
                uint32_t bh0, bl0, bh1, bl1;
                tf32split(ws[n * XST + kb],     bh0, bl0);
                tf32split(ws[n * XST + kb + 4], bh1, bl1);
#pragma unroll
                for (int mi = 0; mi < 2; ++mi) {
                    MMA(acc[mi][ni], ah[mi][0], ah[mi][1], ah[mi][2], ah[mi][3], bh0, bh1);
                    MMA(acc[mi][ni], ah[mi][0], ah[mi][1], ah[mi][2], ah[mi][3], bl0, bl1);
                    MMA(acc[mi][ni], al[mi][0], al[mi][1], al[mi][2], al[mi][3], bh0, bh1);
                }
            }
        }
    }

#pragma unroll
    for (int mi = 0; mi < 2; ++mi) {
        int r0 = row0 + wm * 32 + mi * 16 + lq;
#pragma unroll
        for (int ni = 0; ni < 8; ++ni) {
            int col = wn * 64 + ni * 8 + lr * 2;
            if (r0 < n1)
                *(float2*)&g_xW[(size_t)r0 * H + col] =
                    make_float2(acc[mi][ni][0], acc[mi][ni][1]);
            if (r0 + 8 < n1)
                *(float2*)&g_xW[(size_t)(r0 + 8) * H + col] =
                    make_float2(acc[mi][ni][2], acc[mi][ni][3]);
        }
    }
}

// ---- K6: GCN gather (t<n2) + tail copy (n2<=t<n1), warp per target ------------
__global__ void __launch_bounds__(256) k_gather_gcn(
    const float* __restrict__ b, const int* __restrict__ n1p, int N0, int n2) {
    int t = blockIdx.x * 8 + (threadIdx.x >> 5);
    int n1 = clamp_n1(n1p, N0);
    if (t >= n1) return;
    int lane = threadIdx.x & 31;
    int c4 = lane * 4;
    float4 bb = *(const float4*)&b[c4];
    float4 xw = *(const float4*)&g_xW[(size_t)t * H + c4];

    if (t >= n2) {  // tail: g1 = xW + b
        xw.x += bb.x; xw.y += bb.y; xw.z += bb.z; xw.w += bb.w;
        *(float4*)&g_g1[(size_t)t * H + c4] = xw;
        return;
    }

    int base = __ldg(&g_off[t]);
    int end  = __ldg(&g_off[t + 1]);
    float4 a0 = make_float4(0.f, 0.f, 0.f, 0.f);
    float4 a1 = a0, a2 = a0, a3 = a0;

    for (int i0 = base; i0 < end; i0 += 32) {
        int idx = i0 + lane;
        int s = 0; float w = 0.f;
        if (idx < end) { s = __ldg(&g_esrc[idx]); w = __ldg(&g_ew[idx]); }
        int cnt = min(32, end - i0);
        int j = 0;
        for (; j + 4 <= cnt; j += 4) {
            int   s0 = __shfl_sync(0xffffffffu, s, j);
            float w0 = __shfl_sync(0xffffffffu, w, j);
            int   s1 = __shfl_sync(0xffffffffu, s, j + 1);
            float w1 = __shfl_sync(0xffffffffu, w, j + 1);
            int   s2 = __shfl_sync(0xffffffffu, s, j + 2);
            float w2 = __shfl_sync(0xffffffffu, w, j + 2);
            int   s3 = __shfl_sync(0xffffffffu, s, j + 3);
            float w3 = __shfl_sync(0xffffffffu, w, j + 3);
            float4 v0 = *(const float4*)&g_xW[(size_t)s0 * H + c4];
            float4 v1 = *(const float4*)&g_xW[(size_t)s1 * H + c4];
            float4 v2 = *(const float4*)&g_xW[(size_t)s2 * H + c4];
            float4 v3 = *(const float4*)&g_xW[(size_t)s3 * H + c4];
            a0.x += w0 * v0.x; a0.y += w0 * v0.y; a0.z += w0 * v0.z; a0.w += w0 * v0.w;
            a1.x += w1 * v1.x; a1.y += w1 * v1.y; a1.z += w1 * v1.z; a1.w += w1 * v1.w;
            a2.x += w2 * v2.x; a2.y += w2 * v2.y; a2.z += w2 * v2.z; a2.w += w2 * v2.w;
            a3.x += w3 * v3.x; a3.y += w3 * v3.y; a3.z += w3 * v3.z; a3.w += w3 * v3.w;
        }
        for (; j < cnt; ++j) {
            int   s0 = __shfl_sync(0xffffffffu, s, j);
            float w0 = __shfl_sync(0xffffffffu, w, j);
            float4 v0 = *(const float4*)&g_xW[(size_t)s0 * H + c4];
            a0.x += w0 * v0.x; a0.y += w0 * v0.y; a0.z += w0 * v0.z; a0.w += w0 * v0.w;
        }
    }
    float di = g_dinv[t];
    float d2 = di * di;
    float4 o;
    o.x = (a0.x + a1.x) + (a2.x + a3.x) + xw.x * d2 + bb.x;
    o.y = (a0.y + a1.y) + (a2.y + a3.y) + xw.y * d2 + bb.y;
    o.z = (a0.z + a1.z) + (a2.z + a3.z) + xw.z * d2 + bb.z;
    o.w = (a0.w + a1.w) + (a2.w + a3.w) + xw.w * d2 + bb.w;
    *(float4*)&g_g1[(size_t)t * H + c4] = o;
}

// ---- K7: SAGE gather: s[t] = mean(g1[src]) -------------------------------------
__global__ void __launch_bounds__(256) k_gather_sage(int n2) {
    int t = blockIdx.x * 8 + (threadIdx.x >> 5);
    if (t >= n2) return;
    int lane = threadIdx.x & 31;
    int c4 = lane * 4;
    int base = __ldg(&g_off[t]);
    int end  = __ldg(&g_off[t + 1]);
    float4 a0 = make_float4(0.f, 0.f, 0.f, 0.f);
    float4 a1 = a0, a2 = a0, a3 = a0;

    for (int i0 = base; i0 < end; i0 += 32) {
        int idx = i0 + lane;
        int s = 0;
        if (idx < end) s = __ldg(&g_esrc[idx]);
        int cnt = min(32, end - i0);
        int j = 0;
        for (; j + 4 <= cnt; j += 4) {
            int s0 = __shfl_sync(0xffffffffu, s, j);
            int s1 = __shfl_sync(0xffffffffu, s, j + 1);
            int s2 = __shfl_sync(0xffffffffu, s, j + 2);
            int s3 = __shfl_sync(0xffffffffu, s, j + 3);
            float4 v0 = *(const float4*)&g_g1[(size_t)s0 * H + c4];
            float4 v1 = *(const float4*)&g_g1[(size_t)s1 * H + c4];
            float4 v2 = *(const float4*)&g_g1[(size_t)s2 * H + c4];
            float4 v3 = *(const float4*)&g_g1[(size_t)s3 * H + c4];
            a0.x += v0.x; a0.y += v0.y; a0.z += v0.z; a0.w += v0.w;
            a1.x += v1.x; a1.y += v1.y; a1.z += v1.z; a1.w += v1.w;
            a2.x += v2.x; a2.y += v2.y; a2.z += v2.z; a2.w += v2.w;
            a3.x += v3.x; a3.y += v3.y; a3.z += v3.z; a3.w += v3.w;
        }
        for (; j < cnt; ++j) {
            int s0 = __shfl_sync(0xffffffffu, s, j);
            float4 v0 = *(const float4*)&g_g1[(size_t)s0 * H + c4];
            a0.x += v0.x; a0.y += v0.y; a0.z += v0.z; a0.w += v0.w;
        }
    }
    float inv = 1.f / fmaxf((float)(end - base), 1.f);
    float4 o;
    o.x = ((a0.x + a1.x) + (a2.x + a3.x)) * inv;
    o.y = ((a0.y + a1.y) + (a2.y + a3.y)) * inv;
    o.z = ((a0.z + a1.z) + (a2.z + a3.z)) * inv;
    o.w = ((a0.w + a1.w) + (a2.w + a3.w)) * inv;
    *(float4*)&g_s[(size_t)t * H + c4] = o;
}

// ---- K8: out = l2norm( mean @ Wl^T + bl + g1 @ Wr^T ) --------------------------
__global__ void __launch_bounds__(256) k_sage_out(
    const float* __restrict__ Wl, const float* __restrict__ bl,
    const float* __restrict__ Wr, int n2, float* __restrict__ out) {
    extern __shared__ float sm[];
    float* Wlt  = sm;
    float* Wrt  = Wlt + H * SW;
    float* ms   = Wrt + H * SW;
    float* gs   = ms  + H * SX;
    float* psum = gs  + H * SX;
    float* scl  = psum + GROWS * 16;

    int row0 = blockIdx.x * GROWS;
    int tid = threadIdx.x;

    for (int idx = tid; idx < H * H; idx += 256) {
        int j = idx >> 7, k = idx & 127;
        Wlt[k * SW + j] = Wl[idx];
        Wrt[k * SW + j] = Wr[idx];
    }
    for (int idx = tid; idx < GROWS * H; idx += 256) {
        int r = idx >> 7, k = idx & 127;
        int row = row0 + r;
        if (row < n2) {
            size_t off = (size_t)row * H + k;
            ms[k * SX + r] = g_s[off];
            gs[k * SX + r] = g_g1[off];
        } else {
            ms[k * SX + r] = 0.f;
            gs[k * SX + r] = 0.f;
        }
    }
    __syncthreads();

    int col_t = tid & 15;
    int row_t = tid >> 4;
    float acc[4][8];
#pragma unroll
    for (int j = 0; j < 8; ++j) {
        float bv = bl[col_t * 8 + j];
#pragma unroll
        for (int i = 0; i < 4; ++i) acc[i][j] = bv;
    }

    for (int k = 0; k < H; ++k) {
        float4 am4 = *(const float4*)&ms[k * SX + row_t * 4];
        float4 ag4 = *(const float4*)&gs[k * SX + row_t * 4];
        float4 l0 = *(const float4*)&Wlt[k * SW + col_t * 8];
        float4 l1 = *(const float4*)&Wlt[k * SW + col_t * 8 + 4];
        float4 r0 = *(const float4*)&Wrt[k * SW + col_t * 8];
        float4 r1 = *(const float4*)&Wrt[k * SW + col_t * 8 + 4];
        float am[4] = {am4.x, am4.y, am4.z, am4.w};
        float ag[4] = {ag4.x, ag4.y, ag4.z, ag4.w};
        float wl[8] = {l0.x, l0.y, l0.z, l0.w, l1.x, l1.y, l1.z, l1.w};
        float wr[8] = {r0.x, r0.y, r0.z, r0.w, r1.x, r1.y, r1.z, r1.w};
#pragma unroll
        for (int i = 0; i < 4; ++i)
#pragma unroll
            for (int j = 0; j < 8; ++j)
                acc[i][j] += am[i] * wl[j] + ag[i] * wr[j];
    }

#pragma unroll
    for (int i = 0; i < 4; ++i) {
        float loc = 0.f;
#pragma unroll
        for (int j = 0; j < 8; ++j) loc += acc[i][j] * acc[i][j];
        psum[(row_t * 4 + i) * 16 + col_t] = loc;
    }
    __syncthreads();
    if (tid < GROWS) {
        float ssum = 0.f;
#pragma unroll
        for (int c = 0; c < 16; ++c) ssum += psum[tid * 16 + c];
        scl[tid] = 1.f / fmaxf(sqrtf(ssum), 1e-12f);
    }
    __syncthreads();

#pragma unroll
    for (int i = 0; i < 4; ++i) {
        int row = row0 + row_t * 4 + i;
        if (row < n2) {
            float sc = scl[row_t * 4 + i];
            float4 o0 = make_float4(acc[i][0] * sc, acc[i][1] * sc,
                                    acc[i][2] * sc, acc[i][3] * sc);
            float4 o1 = make_float4(acc[i][4] * sc, acc[i][5] * sc,
                                    acc[i][6] * sc, acc[i][7] * sc);
            *(float4*)&out[(size_t)row * H + col_t * 8]     = o0;
            *(float4*)&out[(size_t)row * H + col_t * 8 + 4] = o1;
        }
    }
}

// ---------------------------------------------------------------------------
extern "C" void kernel_launch(void* const* d_in, const int* in_sizes, int n_in,
                              void* d_out, int out_size) {
    const float* x     = (const float*)d_in[0];
    const float* attr  = (const float*)d_in[1];
    const int*   e_id1 = (const int*)d_in[3];
    const int*   src1  = (const int*)d_in[6];
    const int*   tgt1  = (const int*)d_in[7];
    const int*   n1p   = (const int*)d_in[8];
    const float* gcn_W = (const float*)d_in[10];
    const float* gcn_b = (const float*)d_in[11];
    const float* Wl1   = (const float*)d_in[15];
    const float* bl1   = (const float*)d_in[16];
    const float* Wr1   = (const float*)d_in[17];
    float* out = (float*)d_out;

    int N0 = in_sizes[0] / H;  if (N0 > MAXN0) N0 = MAXN0;
    int E1 = in_sizes[3];      if (E1 > MAXE)  E1 = MAXE;
    int n2 = out_size / H;     if (n2 > MAXN2) n2 = MAXN2;

    constexpr int SMEM_GEMM = 128 * XST * 2 * 4;
    constexpr int SMEM_K8 = (2 * H * SW + 2 * H * SX + GROWS * 16 + GROWS) * 4;
    cudaFuncSetAttribute(k_gemm_tc, cudaFuncAttributeMaxDynamicSharedMemorySize, SMEM_GEMM);
    cudaFuncSetAttribute(k_sage_out, cudaFuncAttributeMaxDynamicSharedMemorySize, SMEM_K8);

    // Fork: GEMM on side stream, edge preprocessing on main stream.
    cudaStream_t s2;
    cudaStreamCreateWithFlags(&s2, cudaStreamNonBlocking);
    cudaEvent_t evFork, evGemm;
    cudaEventCreateWithFlags(&evFork, cudaEventDisableTiming);
    cudaEventCreateWithFlags(&evGemm, cudaEventDisableTiming);

    cudaEventRecord(evFork, 0);
    cudaStreamWaitEvent(s2, evFork, 0);
    k_gemm_tc<<<(N0 + 127) / 128, 256, SMEM_GEMM, s2>>>(x, gcn_W, n1p, N0);
    cudaEventRecord(evGemm, s2);

    k_init<<<(n2 + 255) / 256, 256>>>(n2);
    k_hist<<<(E1 + 255) / 256, 256>>>(attr, e_id1, tgt1, E1, n2);
    k_scan_dinv<<<1, 1024>>>(n2);
    k_scatter<<<(E1 + 255) / 256, 256>>>(attr, e_id1, src1, tgt1, E1, n2);

    cudaStreamWaitEvent(0, evGemm, 0);  // join

    k_gather_gcn<<<(N0 + 7) / 8, 256>>>(gcn_b, n1p, N0, n2);
    k_gather_sage<<<(n2 + 7) / 8, 256>>>(n2);
    k_sage_out<<<(n2 + GROWS - 1) / GROWS, 256, SMEM_K8>>>(Wl1, bl1, Wr1, n2, out);
}

// round 5
// speedup vs baseline: 1.6005x; 1.0029x over previous
#include <cuda_runtime.h>
#include <cuda_fp16.h>
#include <cstdint>

// ---------------------------------------------------------------------------
// GlobalGNN layer-1-only pipeline:
//   xW   = x @ gcn_W^T   (tf32 TC GEMM -> fp16 storage)  [stream 2, overlapped]
//   CSR build over (src1,tgt1) with per-edge norm        [stream 1]
//   g1[t<n2]  = gather(norm * xW[src]) + xW[t]*dinv^2 + b ; g1[n2..n1)=xW+b
//   mean[t]   = gather(g1[src]) / max(cnt,1)
//   out = l2norm( mean @ Wl1^T + bl1 + g1[:n2] @ Wr1^T )
// Gather operands (xW, g1) stored fp16; all accumulation fp32.
// ---------------------------------------------------------------------------

#define H 128
#define MAXN0 131072
#define MAXN2 16384
#define MAXE  1048576
#define GROWS 64
#define SW 132
#define SX 68
#define XST 72

__device__ __align__(16) __half g_xWh[(size_t)MAXN0 * H];   // fp16 xW
__device__ __align__(16) __half g_g1h[(size_t)MAXN0 * H];   // fp16 g1 (all n1 rows)
__device__ __align__(16) float  g_g1f[(size_t)MAXN2 * H];   // fp32 g1 (rows < n2)
__device__ __align__(16) float  g_s  [(size_t)MAXN2 * H];
__device__ float g_degx[MAXN2];   // sum of in-edge weights (deg = 1 + degx)
__device__ float g_dinv[MAXN2];
__device__ int   g_hist[MAXN2];
__device__ int   g_cur [MAXN2];
__device__ int   g_off [MAXN2 + 1];
__device__ int   g_esrc[MAXE];
__device__ float g_ew  [MAXE];

__device__ __forceinline__ int clamp_n1(const int* p, int N0) {
    int v = *p;
    if (v <= 0 || v > N0) v = N0;
    return v;
}

__device__ __forceinline__ void tf32split(float f, uint32_t& hi, uint32_t& lo) {
    uint32_t h;
    asm("cvt.rna.tf32.f32 %0, %1;" : "=r"(h) : "f"(f));
    float r = f - __uint_as_float(h);
    asm("cvt.rna.tf32.f32 %0, %1;" : "=r"(lo) : "f"(r));
    hi = h;
}

__device__ __forceinline__ float4 h4_to_f4(uint2 raw) {
    __half2 h0 = *reinterpret_cast<__half2*>(&raw.x);
    __half2 h1 = *reinterpret_cast<__half2*>(&raw.y);
    float2 f0 = __half22float2(h0);
    float2 f1 = __half22float2(h1);
    return make_float4(f0.x, f0.y, f1.x, f1.y);
}

__device__ __forceinline__ uint2 f4_to_h4(float4 v) {
    __half2 h0 = __floats2half2_rn(v.x, v.y);
    __half2 h1 = __floats2half2_rn(v.z, v.w);
    uint2 r;
    r.x = *reinterpret_cast<uint32_t*>(&h0);
    r.y = *reinterpret_cast<uint32_t*>(&h1);
    return r;
}

#define MMA(d, a0, a1, a2, a3, b0, b1)                                        \
    asm volatile(                                                             \
        "mma.sync.aligned.m16n8k8.row.col.f32.tf32.tf32.f32 "                 \
        "{%0,%1,%2,%3},{%4,%5,%6,%7},{%8,%9},{%0,%1,%2,%3};"                  \
        : "+f"(d[0]), "+f"(d[1]), "+f"(d[2]), "+f"(d[3])                      \
        : "r"(a0), "r"(a1), "r"(a2), "r"(a3), "r"(b0), "r"(b1))

// ---- K1: histogram + weighted degree ----------------------------------------
__global__ void k_hist(const float* __restrict__ attr, const int* __restrict__ eid,
                       const int* __restrict__ tgt, int E, int n2) {
    int e = blockIdx.x * blockDim.x + threadIdx.x;
    if (e >= E) return;
    int t = __ldg(&tgt[e]);
    if (t >= n2) return;
    atomicAdd(&g_hist[t], 1);
    atomicAdd(&g_degx[t], __ldg(&attr[__ldg(&eid[e])]));
}

// ---- K2: dinv = rsqrt(1 + degx), grid-wide ------------------------------------
__global__ void k_dinv(int n2) {
    int i = blockIdx.x * blockDim.x + threadIdx.x;
    if (i < n2) g_dinv[i] = rsqrtf(1.f + g_degx[i]);
}

// ---- K3: exclusive scan, single block, dynamic-smem staged --------------------
__global__ void __launch_bounds__(1024) k_scan(int n2) {
    extern __shared__ int sh[];          // 16384 ints = 64 KB (dynamic)
    __shared__ int wsum[32];
    int tid = threadIdx.x, lane = tid & 31, wid = tid >> 5;
    for (int i = tid; i < 16384; i += 1024) sh[i] = (i < n2) ? g_hist[i] : 0;
    __syncthreads();
    int base = tid * 16;
    int vals[16];
    int local = 0;
#pragma unroll
    for (int i = 0; i < 16; ++i) { vals[i] = local; local += sh[base + i]; }
    int inc = local;
#pragma unroll
    for (int off = 1; off < 32; off <<= 1) {
        int nb = __shfl_up_sync(0xffffffffu, inc, off);
        if (lane >= off) inc += nb;
    }
    if (lane == 31) wsum[wid] = inc;
    __syncthreads();
    if (wid == 0) {
        int s = wsum[lane];
#pragma unroll
        for (int off = 1; off < 32; off <<= 1) {
            int nb = __shfl_up_sync(0xffffffffu, s, off);
            if (lane >= off) s += nb;
        }
        wsum[lane] = s;
    }
    __syncthreads();
    int excl = ((wid > 0) ? wsum[wid - 1] : 0) + inc - local;
#pragma unroll
    for (int i = 0; i < 16; ++i) sh[base + i] = excl + vals[i];
    int total = wsum[31];
    __syncthreads();
    for (int i = tid; i < n2; i += 1024) g_off[i] = sh[i];
    if (tid == 0) g_off[n2] = total;
}

// ---- K4: scatter edges into CSR, precompute norm ------------------------------
__global__ void k_scatter(const float* __restrict__ attr, const int* __restrict__ eid,
                          const int* __restrict__ src, const int* __restrict__ tgt,
                          int E, int n2) {
    int e = blockIdx.x * blockDim.x + threadIdx.x;
    if (e >= E) return;
    int t = __ldg(&tgt[e]);
    if (t >= n2) return;
    int pos = g_off[t] + atomicAdd(&g_cur[t], 1);
    int s = __ldg(&src[e]);
    float w = __ldg(&attr[__ldg(&eid[e])]);
    float ds = (s < n2) ? g_dinv[s] : 1.f;
    g_esrc[pos] = s;
    g_ew[pos] = ds * w * g_dinv[t];
}

// ---- K5: xW = x @ W^T via tf32 TC, fp16 output (rows < n1) --------------------
__global__ void __launch_bounds__(256) k_gemm_tc(
    const float* __restrict__ x, const float* __restrict__ W,
    const int* __restrict__ n1p, int N0) {
    extern __shared__ float sm[];
    float* xs = sm;
    float* ws = sm + 128 * XST;

    int n1 = clamp_n1(n1p, N0);
    int row0 = blockIdx.x * 128;
    if (row0 >= n1) return;

    int tid = threadIdx.x, lane = tid & 31, warp = tid >> 5;
    int wm = warp >> 1, wn = warp & 1;
    int lq = lane >> 2, lr = lane & 3;

    float acc[2][8][4];
#pragma unroll
    for (int mi = 0; mi < 2; ++mi)
#pragma unroll
        for (int ni = 0; ni < 8; ++ni)
#pragma unroll
            for (int j = 0; j < 4; ++j) acc[mi][ni][j] = 0.f;

    for (int kc = 0; kc < H; kc += 64) {
        if (kc) __syncthreads();
#pragma unroll
        for (int it = 0; it < 8; ++it) {
            int f4 = it * 256 + tid;
            int r = f4 >> 4, k4 = f4 & 15;
            int row = row0 + r;
            float4 v = make_float4(0.f, 0.f, 0.f, 0.f);
            if (row < N0) v = *(const float4*)&x[(size_t)row * H + kc + k4 * 4];
            *(float4*)&xs[r * XST + k4 * 4] = v;
            float4 wv = *(const float4*)&W[(size_t)r * H + kc + k4 * 4];
            *(float4*)&ws[r * XST + k4 * 4] = wv;
        }
        __syncthreads();

#pragma unroll
        for (int ks = 0; ks < 8; ++ks) {
            int kb = ks * 8 + lr;
            uint32_t ah[2][4], al[2][4];
#pragma unroll
            for (int mi = 0; mi < 2; ++mi) {
                int r = wm * 32 + mi * 16 + lq;
                tf32split(xs[r * XST + kb],           ah[mi][0], al[mi][0]);
                tf32split(xs[(r + 8) * XST + kb],     ah[mi][1], al[mi][1]);
                tf32split(xs[r * XST + kb + 4],       ah[mi][2], al[mi][2]);
                tf32split(xs[(r + 8) * XST + kb + 4], ah[mi][3], al[mi][3]);
            }
#pragma unroll
            for (int ni = 0; ni < 8; ++ni) {
                int n = wn * 64 + ni * 8 + lq;
                uint32_t bh0, bl0, bh1, bl1;
                tf32split(ws[n * XST + kb],     bh0, bl0);
                tf32split(ws[n * XST + kb + 4], bh1, bl1);
#pragma unroll
                for (int mi = 0; mi < 2; ++mi) {
                    MMA(acc[mi][ni], ah[mi][0], ah[mi][1], ah[mi][2], ah[mi][3], bh0, bh1);
                    MMA(acc[mi][ni], ah[mi][0], ah[mi][1], ah[mi][2], ah[mi][3], bl0, bl1);
                    MMA(acc[mi][ni], al[mi][0], al[mi][1], al[mi][2], al[mi][3], bh0, bh1);
                }
            }
        }
    }

#pragma unroll
    for (int mi = 0; mi < 2; ++mi) {
        int r0 = row0 + wm * 32 + mi * 16 + lq;
#pragma unroll
        for (int ni = 0; ni < 8; ++ni) {
            int col = wn * 64 + ni * 8 + lr * 2;
            if (r0 < n1) {
                __half2 h = __floats2half2_rn(acc[mi][ni][0], acc[mi][ni][1]);
                *(__half2*)&g_xWh[(size_t)r0 * H + col] = h;
            }
            if (r0 + 8 < n1) {
                __half2 h = __floats2half2_rn(acc[mi][ni][2], acc[mi][ni][3]);
                *(__half2*)&g_xWh[(size_t)(r0 + 8) * H + col] = h;
            }
        }
    }
}

// ---- K6: GCN gather (t<n2) + tail (n2<=t<n1), warp per target -----------------
__global__ void __launch_bounds__(256) k_gather_gcn(
    const float* __restrict__ b, const int* __restrict__ n1p, int N0, int n2) {
    int t = blockIdx.x * 8 + (threadIdx.x >> 5);
    int n1 = clamp_n1(n1p, N0);
    if (t >= n1) return;
    int lane = threadIdx.x & 31;
    int c = lane * 4;
    float4 bb = *(const float4*)&b[c];
    float4 xw = h4_to_f4(*(const uint2*)&g_xWh[(size_t)t * H + c]);

    if (t >= n2) {  // tail: g1 = xW + b (fp16 only)
        xw.x += bb.x; xw.y += bb.y; xw.z += bb.z; xw.w += bb.w;
        *(uint2*)&g_g1h[(size_t)t * H + c] = f4_to_h4(xw);
        return;
    }

    int base = __ldg(&g_off[t]);
    int end  = __ldg(&g_off[t + 1]);
    float4 a0 = make_float4(0.f, 0.f, 0.f, 0.f);
    float4 a1 = a0, a2 = a0, a3 = a0;

    for (int i0 = base; i0 < end; i0 += 32) {
        int idx = i0 + lane;
        int s = 0; float w = 0.f;
        if (idx < end) { s = __ldg(&g_esrc[idx]); w = __ldg(&g_ew[idx]); }
        int cnt = min(32, end - i0);
        int j = 0;
        for (; j + 4 <= cnt; j += 4) {
            int   s0 = __shfl_sync(0xffffffffu, s, j);
            float w0 = __shfl_sync(0xffffffffu, w, j);
            int   s1 = __shfl_sync(0xffffffffu, s, j + 1);
            float w1 = __shfl_sync(0xffffffffu, w, j + 1);
            int   s2 = __shfl_sync(0xffffffffu, s, j + 2);
            float w2 = __shfl_sync(0xffffffffu, w, j + 2);
            int   s3 = __shfl_sync(0xffffffffu, s, j + 3);
            float w3 = __shfl_sync(0xffffffffu, w, j + 3);
            float4 v0 = h4_to_f4(*(const uint2*)&g_xWh[(size_t)s0 * H + c]);
            float4 v1 = h4_to_f4(*(const uint2*)&g_xWh[(size_t)s1 * H + c]);
            float4 v2 = h4_to_f4(*(const uint2*)&g_xWh[(size_t)s2 * H + c]);
            float4 v3 = h4_to_f4(*(const uint2*)&g_xWh[(size_t)s3 * H + c]);
            a0.x += w0 * v0.x; a0.y += w0 * v0.y; a0.z += w0 * v0.z; a0.w += w0 * v0.w;
            a1.x += w1 * v1.x; a1.y += w1 * v1.y; a1.z += w1 * v1.z; a1.w += w1 * v1.w;
            a2.x += w2 * v2.x; a2.y += w2 * v2.y; a2.z += w2 * v2.z; a2.w += w2 * v2.w;
            a3.x += w3 * v3.x; a3.y += w3 * v3.y; a3.z += w3 * v3.z; a3.w += w3 * v3.w;
        }
        for (; j < cnt; ++j) {
            int   s0 = __shfl_sync(0xffffffffu, s, j);
            float w0 = __shfl_sync(0xffffffffu, w, j);
            float4 v0 = h4_to_f4(*(const uint2*)&g_xWh[(size_t)s0 * H + c]);
            a0.x += w0 * v0.x; a0.y += w0 * v0.y; a0.z += w0 * v0.z; a0.w += w0 * v0.w;
        }
    }
    float di = g_dinv[t];
    float d2 = di * di;
    float4 o;
    o.x = (a0.x + a1.x) + (a2.x + a3.x) + xw.x * d2 + bb.x;
    o.y = (a0.y + a1.y) + (a2.y + a3.y) + xw.y * d2 + bb.y;
    o.z = (a0.z + a1.z) + (a2.z + a3.z) + xw.z * d2 + bb.z;
    o.w = (a0.w + a1.w) + (a2.w + a3.w) + xw.w * d2 + bb.w;
    *(float4*)&g_g1f[(size_t)t * H + c] = o;          // fp32 for sage_out
    *(uint2*)&g_g1h[(size_t)t * H + c] = f4_to_h4(o); // fp16 for sage gather
}

// ---- K7: SAGE gather: s[t] = mean(g1[src]) -------------------------------------
__global__ void __launch_bounds__(256) k_gather_sage(int n2) {
    int t = blockIdx.x * 8 + (threadIdx.x >> 5);
    if (t >= n2) return;
    int lane = threadIdx.x & 31;
    int c = lane * 4;
    int base = __ldg(&g_off[t]);
    int end  = __ldg(&g_off[t + 1]);
    float4 a0 = make_float4(0.f, 0.f, 0.f, 0.f);
    float4 a1 = a0, a2 = a0, a3 = a0;

    for (int i0 = base; i0 < end; i0 += 32) {
        int idx = i0 + lane;
        int s = 0;
        if (idx < end) s = __ldg(&g_esrc[idx]);
        int cnt = min(32, end - i0);
        int j = 0;
        for (; j + 4 <= cnt; j += 4) {
            int s0 = __shfl_sync(0xffffffffu, s, j);
            int s1 = __shfl_sync(0xffffffffu, s, j + 1);
            int s2 = __shfl_sync(0xffffffffu, s, j + 2);
            int s3 = __shfl_sync(0xffffffffu, s, j + 3);
            float4 v0 = h4_to_f4(*(const uint2*)&g_g1h[(size_t)s0 * H + c]);
            float4 v1 = h4_to_f4(*(const uint2*)&g_g1h[(size_t)s1 * H + c]);
            float4 v2 = h4_to_f4(*(const uint2*)&g_g1h[(size_t)s2 * H + c]);
            float4 v3 = h4_to_f4(*(const uint2*)&g_g1h[(size_t)s3 * H + c]);
            a0.x += v0.x; a0.y += v0.y; a0.z += v0.z; a0.w += v0.w;
            a1.x += v1.x; a1.y += v1.y; a1.z += v1.z; a1.w += v1.w;
            a2.x += v2.x; a2.y += v2.y; a2.z += v2.z; a2.w += v2.w;
            a3.x += v3.x; a3.y += v3.y; a3.z += v3.z; a3.w += v3.w;
        }
        for (; j < cnt; ++j) {
            int s0 = __shfl_sync(0xffffffffu, s, j);
            float4 v0 = h4_to_f4(*(const uint2*)&g_g1h[(size_t)s0 * H + c]);
            a0.x += v0.x; a0.y += v0.y; a0.z += v0.z; a0.w += v0.w;
        }
    }
    float inv = 1.f / fmaxf((float)(end - base), 1.f);
    float4 o;
    o.x = ((a0.x + a1.x) + (a2.x + a3.x)) * inv;
    o.y = ((a0.y + a1.y) + (a2.y + a3.y)) * inv;
    o.z = ((a0.z + a1.z) + (a2.z + a3.z)) * inv;
    o.w = ((a0.w + a1.w) + (a2.w + a3.w)) * inv;
    *(float4*)&g_s[(size_t)t * H + c] = o;
}

// ---- K8: out = l2norm( mean @ Wl^T + bl + g1 @ Wr^T ) --------------------------
__global__ void __launch_bounds__(256) k_sage_out(
    const float* __restrict__ Wl, const float* __restrict__ bl,
    const float* __restrict__ Wr, int n2, float* __restrict__ out) {
    extern __shared__ float sm[];
    float* Wlt  = sm;
    float* Wrt  = Wlt + H * SW;
    float* ms   = Wrt + H * SW;
    float* gs   = ms  + H * SX;
    float* psum = gs  + H * SX;
    float* scl  = psum + GROWS * 16;

    int row0 = blockIdx.x * GROWS;
    int tid = threadIdx.x;

    for (int idx = tid; idx < H * H; idx += 256) {
        int j = idx >> 7, k = idx & 127;
        Wlt[k * SW + j] = Wl[idx];
        Wrt[k * SW + j] = Wr[idx];
    }
    for (int idx = tid; idx < GROWS * H; idx += 256) {
        int r = idx >> 7, k = idx & 127;
        int row = row0 + r;
        if (row < n2) {
            size_t off = (size_t)row * H + k;
            ms[k * SX + r] = g_s[off];
            gs[k * SX + r] = g_g1f[off];
        } else {
            ms[k * SX + r] = 0.f;
            gs[k * SX + r] = 0.f;
        }
    }
    __syncthreads();

    int col_t = tid & 15;
    int row_t = tid >> 4;
    float acc[4][8];
#pragma unroll
    for (int j = 0; j < 8; ++j) {
        float bv = bl[col_t * 8 + j];
#pragma unroll
        for (int i = 0; i < 4; ++i) acc[i][j] = bv;
    }

    for (int k = 0; k < H; ++k) {
        float4 am4 = *(const float4*)&ms[k * SX + row_t * 4];
        float4 ag4 = *(const float4*)&gs[k * SX + row_t * 4];
        float4 l0 = *(const float4*)&Wlt[k * SW + col_t * 8];
        float4 l1 = *(const float4*)&Wlt[k * SW + col_t * 8 + 4];
        float4 r0 = *(const float4*)&Wrt[k * SW + col_t * 8];
        float4 r1 = *(const float4*)&Wrt[k * SW + col_t * 8 + 4];
        float am[4] = {am4.x, am4.y, am4.z, am4.w};
        float ag[4] = {ag4.x, ag4.y, ag4.z, ag4.w};
        float wl[8] = {l0.x, l0.y, l0.z, l0.w, l1.x, l1.y, l1.z, l1.w};
        float wr[8] = {r0.x, r0.y, r0.z, r0.w, r1.x, r1.y, r1.z, r1.w};
#pragma unroll
        for (int i = 0; i < 4; ++i)
#pragma unroll
            for (int j = 0; j < 8; ++j)
                acc[i][j] += am[i] * wl[j] + ag[i] * wr[j];
    }

#pragma unroll
    for (int i = 0; i < 4; ++i) {
        float loc = 0.f;
#pragma unroll
        for (int j = 0; j < 8; ++j) loc += acc[i][j] * acc[i][j];
        psum[(row_t * 4 + i) * 16 + col_t] = loc;
    }
    __syncthreads();
    if (tid < GROWS) {
        float ssum = 0.f;
#pragma unroll
        for (int cc = 0; cc < 16; ++cc) ssum += psum[tid * 16 + cc];
        scl[tid] = 1.f / fmaxf(sqrtf(ssum), 1e-12f);
    }
    __syncthreads();

#pragma unroll
    for (int i = 0; i < 4; ++i) {
        int row = row0 + row_t * 4 + i;
        if (row < n2) {
            float sc = scl[row_t * 4 + i];
            float4 o0 = make_float4(acc[i][0] * sc, acc[i][1] * sc,
                                    acc[i][2] * sc, acc[i][3] * sc);
            float4 o1 = make_float4(acc[i][4] * sc, acc[i][5] * sc,
                                    acc[i][6] * sc, acc[i][7] * sc);
            *(float4*)&out[(size_t)row * H + col_t * 8]     = o0;
            *(float4*)&out[(size_t)row * H + col_t * 8 + 4] = o1;
        }
    }
}

// ---------------------------------------------------------------------------
extern "C" void kernel_launch(void* const* d_in, const int* in_sizes, int n_in,
                              void* d_out, int out_size) {
    const float* x     = (const float*)d_in[0];
    const float* attr  = (const float*)d_in[1];
    const int*   e_id1 = (const int*)d_in[3];
    const int*   src1  = (const int*)d_in[6];
    const int*   tgt1  = (const int*)d_in[7];
    const int*   n1p   = (const int*)d_in[8];
    const float* gcn_W = (const float*)d_in[10];
    const float* gcn_b = (const float*)d_in[11];
    const float* Wl1   = (const float*)d_in[15];
    const float* bl1   = (const float*)d_in[16];
    const float* Wr1   = (const float*)d_in[17];
    float* out = (float*)d_out;

    int N0 = in_sizes[0] / H;  if (N0 > MAXN0) N0 = MAXN0;
    int E1 = in_sizes[3];      if (E1 > MAXE)  E1 = MAXE;
    int n2 = out_size / H;     if (n2 > MAXN2) n2 = MAXN2;

    constexpr int SMEM_GEMM = 128 * XST * 2 * 4;
    constexpr int SMEM_SCAN = 16384 * 4;
    constexpr int SMEM_K8 = (2 * H * SW + 2 * H * SX + GROWS * 16 + GROWS) * 4;
    cudaFuncSetAttribute(k_gemm_tc, cudaFuncAttributeMaxDynamicSharedMemorySize, SMEM_GEMM);
    cudaFuncSetAttribute(k_scan, cudaFuncAttributeMaxDynamicSharedMemorySize, SMEM_SCAN);
    cudaFuncSetAttribute(k_sage_out, cudaFuncAttributeMaxDynamicSharedMemorySize, SMEM_K8);

    void *p_hist, *p_degx, *p_cur;
    cudaGetSymbolAddress(&p_hist, g_hist);
    cudaGetSymbolAddress(&p_degx, g_degx);
    cudaGetSymbolAddress(&p_cur,  g_cur);

    cudaStream_t s2;
    cudaStreamCreateWithFlags(&s2, cudaStreamNonBlocking);
    cudaEvent_t evFork, evGemm;
    cudaEventCreateWithFlags(&evFork, cudaEventDisableTiming);
    cudaEventCreateWithFlags(&evGemm, cudaEventDisableTiming);

    // Fork: GEMM on side stream.
    cudaEventRecord(evFork, 0);
    cudaStreamWaitEvent(s2, evFork, 0);
    k_gemm_tc<<<(N0 + 127) / 128, 256, SMEM_GEMM, s2>>>(x, gcn_W, n1p, N0);
    cudaEventRecord(evGemm, s2);

    // Main stream: edge preprocessing.
    cudaMemsetAsync(p_hist, 0, (size_t)n2 * 4, 0);
    cudaMemsetAsync(p_degx, 0, (size_t)n2 * 4, 0);
    cudaMemsetAsync(p_cur,  0, (size_t)n2 * 4, 0);
    k_hist<<<(E1 + 255) / 256, 256>>>(attr, e_id1, tgt1, E1, n2);
    k_dinv<<<(n2 + 255) / 256, 256>>>(n2);
    k_scan<<<1, 1024, SMEM_SCAN>>>(n2);
    k_scatter<<<(E1 + 255) / 256, 256>>>(attr, e_id1, src1, tgt1, E1, n2);

    cudaStreamWaitEvent(0, evGemm, 0);  // join

    k_gather_gcn<<<(N0 + 7) / 8, 256>>>(gcn_b, n1p, N0, n2);
    k_gather_sage<<<(n2 + 7) / 8, 256>>>(n2);
    k_sage_out<<<(n2 + GROWS - 1) / GROWS, 256, SMEM_K8>>>(Wl1, bl1, Wr1, n2, out);
}